// round 9
// baseline (speedup 1.0000x reference)
#include <cuda_runtime.h>
#include <math.h>

#define IN_DIM 8
#define HID 50
#define KTOT 58            // 50 h-rows + 8 x-rows unified
#define BATCH 4096
#define TLEN 512
#define ROWS 150
#define RPAD 164
#define NB 32
#define NT 256
#define GRIDN (BATCH / NB)
#define HXS (KTOT * NB)    // one hx buffer
#define WPT 12             // floats per tile: {wr0,wr0,wr1,wr1,wz0,wz0,wz1,wz1,wn0,wn0,wn1,wn1}

typedef unsigned long long ull;

__device__ __forceinline__ ull pk2(float a) {
    ull r; asm("mov.b64 %0, {%1, %1};" : "=l"(r) : "f"(a)); return r;
}
__device__ __forceinline__ ull ff2(ull a, ull b, ull c) {
    ull d; asm("fma.rn.f32x2 %0, %1, %2, %3;" : "=l"(d) : "l"(a), "l"(b), "l"(c));
    return d;
}
__device__ __forceinline__ ull add2(ull a, ull b) {
    ull d; asm("add.rn.f32x2 %0, %1, %2;" : "=l"(d) : "l"(a), "l"(b));
    return d;
}
__device__ __forceinline__ float2 up2(ull v) {
    float2 r; asm("mov.b64 {%0, %1}, %2;" : "=f"(r.x), "=f"(r.y) : "l"(v)); return r;
}
__device__ __forceinline__ float tanhapx(float v) {
    float r; asm("tanh.approx.f32 %0, %1;" : "=f"(r) : "f"(v)); return r;
}
__device__ __forceinline__ float fsig(float v) {
    return fmaf(0.5f, tanhapx(0.5f * v), 0.5f);
}

__global__ __launch_bounds__(NT, 1) void gru_kernel(
    const float* __restrict__ x, const float* __restrict__ W_ih,
    const float* __restrict__ W_hh, const float* __restrict__ b_ih,
    const float* __restrict__ b_hh, const float* __restrict__ W_out,
    const float* __restrict__ b_out, float* __restrict__ out)
{
    extern __shared__ float sm[];
    float* Wp = sm;                       // [KTOT][32 tiles][WPT], gate scalars DUPLICATED
    float* bi = Wp + KTOT * 32 * WPT;     // [RPAD] b_ih (zero-padded)
    float* bh = bi + RPAD;                // [RPAD] b_hh
    float* hx = bh + RPAD;                // [2][KTOT][NB]

    const int tid  = threadIdx.x;
    const int lane = tid & 31;
    const int wid  = tid >> 5;
    const int b0   = blockIdx.x * NB;
    const int tile = wid * 4 + (lane >> 3);   // 0..31 (25 live)
    const int c    = tile * 2;
    const int tb4  = (lane & 7) * 4;          // batch group of 4
    const bool live = (c < HID);

    // ---- one-time: pack weights, duplicated per f32x2 lane-pair ----
    for (int i = tid; i < KTOT * 32 * WPT; i += NT) {
        int k  = i / (32 * WPT);
        int r  = i - k * (32 * WPT);
        int tl = r / WPT;
        int q  = r - tl * WPT;
        int g  = q >> 2;            // 0=r,1=z,2=n
        int u  = (q >> 1) & 1;      // c offset
        int cu = tl * 2 + u;
        float v = 0.0f;
        if (cu < HID) {
            int j = g * HID + cu;
            v = (k < HID) ? W_hh[j * HID + k] : W_ih[j * IN_DIM + (k - HID)];
        }
        Wp[i] = v;
    }
    for (int j = tid; j < RPAD; j += NT) {
        bi[j] = (j < ROWS) ? b_ih[j] : 0.0f;
        bh[j] = (j < ROWS) ? b_hh[j] : 0.0f;
    }
    for (int i = tid; i < HID * NB; i += NT) hx[i] = 0.0f;   // zero h rows, buffer 0

    // ---- x duty on warp 7 (all-pad warp): b = lane ----
    float4 xa, xb;
    const float* xrow = nullptr;
    if (wid == 7) {
        xrow = x + (size_t)(b0 + lane) * TLEN * IN_DIM;
        float4 a0 = *(const float4*)&xrow[0];
        float4 a1 = *(const float4*)&xrow[4];
        hx[(HID + 0) * NB + lane] = a0.x; hx[(HID + 1) * NB + lane] = a0.y;
        hx[(HID + 2) * NB + lane] = a0.z; hx[(HID + 3) * NB + lane] = a0.w;
        hx[(HID + 4) * NB + lane] = a1.x; hx[(HID + 5) * NB + lane] = a1.y;
        hx[(HID + 6) * NB + lane] = a1.z; hx[(HID + 7) * NB + lane] = a1.w;
        xa = *(const float4*)&xrow[IN_DIM];
        xb = *(const float4*)&xrow[IN_DIM + 4];
    }
    __syncthreads();

    // bias pairs (duplicated scalars), one-time pk2 outside the loop
    ull bsi[3][2], bbh[3][2];
    #pragma unroll
    for (int g = 0; g < 3; g++)
        #pragma unroll
        for (int u = 0; u < 2; u++) {
            bsi[g][u] = pk2(bi[c + u + 50 * g]);
            bbh[g][u] = pk2(bh[c + u + 50 * g]);
        }

    for (int t = 0; t < TLEN; t++) {
        float* hcur = hx + (t & 1) * HXS;
        float* hnxt = hx + ((t + 1) & 1) * HXS;

        if (wid != 7) {
            // acc[g][u][p]: gate g, row c+u, batch-pair p
            ull acc[3][2][2];
            #pragma unroll
            for (int g = 0; g < 3; g++)
                #pragma unroll
                for (int u = 0; u < 2; u++) {
                    acc[g][u][0] = bsi[g][u];
                    acc[g][u][1] = bsi[g][u];
                }

            // ---- x-part first (k=50..57), acc init = b_ih ----
            #pragma unroll
            for (int k = HID; k < KTOT; k++) {
                const float* wrow = &Wp[(k * 32 + tile) * WPT];
                ulonglong2 wr = *(const ulonglong2*)wrow;        // {wr0,wr0},{wr1,wr1}
                ulonglong2 wz = *(const ulonglong2*)(wrow + 4);
                ulonglong2 wn = *(const ulonglong2*)(wrow + 8);
                ulonglong2 hp = *(const ulonglong2*)&hcur[k * NB + tb4];  // {b0,b1},{b2,b3}
                acc[0][0][0] = ff2(hp.x, wr.x, acc[0][0][0]);
                acc[0][0][1] = ff2(hp.y, wr.x, acc[0][0][1]);
                acc[0][1][0] = ff2(hp.x, wr.y, acc[0][1][0]);
                acc[0][1][1] = ff2(hp.y, wr.y, acc[0][1][1]);
                acc[1][0][0] = ff2(hp.x, wz.x, acc[1][0][0]);
                acc[1][0][1] = ff2(hp.y, wz.x, acc[1][0][1]);
                acc[1][1][0] = ff2(hp.x, wz.y, acc[1][1][0]);
                acc[1][1][1] = ff2(hp.y, wz.y, acc[1][1][1]);
                acc[2][0][0] = ff2(hp.x, wn.x, acc[2][0][0]);
                acc[2][0][1] = ff2(hp.y, wn.x, acc[2][0][1]);
                acc[2][1][0] = ff2(hp.x, wn.y, acc[2][1][0]);
                acc[2][1][1] = ff2(hp.y, wn.y, acc[2][1][1]);
            }
            // snapshot gi_n; add b_hh
            ull gis[2][2];
            #pragma unroll
            for (int u = 0; u < 2; u++) {
                gis[u][0] = acc[2][u][0];
                gis[u][1] = acc[2][u][1];
            }
            #pragma unroll
            for (int g = 0; g < 3; g++)
                #pragma unroll
                for (int u = 0; u < 2; u++) {
                    acc[g][u][0] = add2(acc[g][u][0], bbh[g][u]);
                    acc[g][u][1] = add2(acc[g][u][1], bbh[g][u]);
                }

            // ---- h-part (k=0..49) ----
            #pragma unroll
            for (int k = 0; k < HID; k++) {
                const float* wrow = &Wp[(k * 32 + tile) * WPT];
                ulonglong2 wr = *(const ulonglong2*)wrow;
                ulonglong2 wz = *(const ulonglong2*)(wrow + 4);
                ulonglong2 wn = *(const ulonglong2*)(wrow + 8);
                ulonglong2 hp = *(const ulonglong2*)&hcur[k * NB + tb4];
                acc[0][0][0] = ff2(hp.x, wr.x, acc[0][0][0]);
                acc[0][0][1] = ff2(hp.y, wr.x, acc[0][0][1]);
                acc[0][1][0] = ff2(hp.x, wr.y, acc[0][1][0]);
                acc[0][1][1] = ff2(hp.y, wr.y, acc[0][1][1]);
                acc[1][0][0] = ff2(hp.x, wz.x, acc[1][0][0]);
                acc[1][0][1] = ff2(hp.y, wz.x, acc[1][0][1]);
                acc[1][1][0] = ff2(hp.x, wz.y, acc[1][1][0]);
                acc[1][1][1] = ff2(hp.y, wz.y, acc[1][1][1]);
                acc[2][0][0] = ff2(hp.x, wn.x, acc[2][0][0]);
                acc[2][0][1] = ff2(hp.y, wn.x, acc[2][0][1]);
                acc[2][1][0] = ff2(hp.x, wn.y, acc[2][1][0]);
                acc[2][1][1] = ff2(hp.y, wn.y, acc[2][1][1]);
            }

            // ---- gates in-register; write h(t+1) ----
            if (live) {
                #pragma unroll
                for (int u = 0; u < 2; u++) {
                    float4 ho = *(const float4*)&hcur[(c + u) * NB + tb4];
                    const float* o = (const float*)&ho;
                    float hn[4];
                    #pragma unroll
                    for (int p = 0; p < 2; p++) {
                        float2 sr = up2(acc[0][u][p]);
                        float2 sz = up2(acc[1][u][p]);
                        float2 sn = up2(acc[2][u][p]);
                        float2 gi = up2(gis[u][p]);
                        float r0 = fsig(sr.x), z0 = fsig(sz.x);
                        float n0 = tanhapx(sn.x + (r0 - 1.0f) * (sn.x - gi.x));
                        hn[2 * p]     = n0 + z0 * (o[2 * p] - n0);
                        float r1 = fsig(sr.y), z1 = fsig(sz.y);
                        float n1 = tanhapx(sn.y + (r1 - 1.0f) * (sn.y - gi.y));
                        hn[2 * p + 1] = n1 + z1 * (o[2 * p + 1] - n1);
                    }
                    *(float4*)&hnxt[(c + u) * NB + tb4] =
                        make_float4(hn[0], hn[1], hn[2], hn[3]);
                }
            }
        } else {
            // ---- warp 7: publish x_{t+1}; prefetch x_{t+2} ----
            if (t + 1 < TLEN) {
                hnxt[(HID + 0) * NB + lane] = xa.x; hnxt[(HID + 1) * NB + lane] = xa.y;
                hnxt[(HID + 2) * NB + lane] = xa.z; hnxt[(HID + 3) * NB + lane] = xa.w;
                hnxt[(HID + 4) * NB + lane] = xb.x; hnxt[(HID + 5) * NB + lane] = xb.y;
                hnxt[(HID + 6) * NB + lane] = xb.z; hnxt[(HID + 7) * NB + lane] = xb.w;
                if (t + 2 < TLEN) {
                    xa = *(const float4*)&xrow[(size_t)(t + 2) * IN_DIM];
                    xb = *(const float4*)&xrow[(size_t)(t + 2) * IN_DIM + 4];
                }
            }
        }

        __syncthreads();   // the ONLY barrier per step
    }

    // final h lives in buffer 0
    if (tid < NB) {
        float acc = b_out[0];
        #pragma unroll
        for (int cc = 0; cc < HID; cc++) acc += hx[cc * NB + tid] * W_out[cc];
        out[b0 + tid] = acc;
    }
}

extern "C" void kernel_launch(void* const* d_in, const int* in_sizes, int n_in,
                              void* d_out, int out_size) {
    const float* x     = (const float*)d_in[0];
    const float* W_ih  = (const float*)d_in[1];
    const float* W_hh  = (const float*)d_in[2];
    const float* b_ih  = (const float*)d_in[3];
    const float* b_hh  = (const float*)d_in[4];
    const float* W_out = (const float*)d_in[5];
    const float* b_out = (const float*)d_in[6];
    float* out = (float*)d_out;

    size_t smem = (size_t)(KTOT * 32 * WPT + 2 * RPAD + 2 * HXS) * sizeof(float);
    cudaFuncSetAttribute(gru_kernel,
                         cudaFuncAttributeMaxDynamicSharedMemorySize, (int)smem);
    gru_kernel<<<GRIDN, NT, smem>>>(x, W_ih, W_hh, b_ih, b_hh, W_out, b_out, out);
}

// round 10
// speedup vs baseline: 1.0014x; 1.0014x over previous
#include <cuda_runtime.h>
#include <math.h>

#define IN_DIM 8
#define HID 50
#define KTOT 58            // 50 h-rows + 8 x-rows unified
#define BATCH 4096
#define TLEN 512
#define ROWS 150
#define RPAD 164
#define NB 32
#define NT 256
#define GRIDN (BATCH / NB)
#define HXS (KTOT * NB)    // one hx buffer
#define WKS 384            // Wp floats per k: 3 gates * 32 tiles * 4

typedef unsigned long long ull;

__device__ __forceinline__ ull pk2(float a) {
    ull r; asm("mov.b64 %0, {%1, %1};" : "=l"(r) : "f"(a)); return r;
}
__device__ __forceinline__ ull ff2(ull a, ull b, ull c) {
    ull d; asm("fma.rn.f32x2 %0, %1, %2, %3;" : "=l"(d) : "l"(a), "l"(b), "l"(c));
    return d;
}
__device__ __forceinline__ ull add2(ull a, ull b) {
    ull d; asm("add.rn.f32x2 %0, %1, %2;" : "=l"(d) : "l"(a), "l"(b));
    return d;
}
__device__ __forceinline__ float2 up2(ull v) {
    float2 r; asm("mov.b64 {%0, %1}, %2;" : "=f"(r.x), "=f"(r.y) : "l"(v)); return r;
}
__device__ __forceinline__ float tanhapx(float v) {
    float r; asm("tanh.approx.f32 %0, %1;" : "=f"(r) : "f"(v)); return r;
}
__device__ __forceinline__ float fsig(float v) {
    return fmaf(0.5f, tanhapx(0.5f * v), 0.5f);
}

__global__ __launch_bounds__(NT, 1) void gru_kernel(
    const float* __restrict__ x, const float* __restrict__ W_ih,
    const float* __restrict__ W_hh, const float* __restrict__ b_ih,
    const float* __restrict__ b_hh, const float* __restrict__ W_out,
    const float* __restrict__ b_out, float* __restrict__ out)
{
    extern __shared__ float sm[];
    float* Wp = sm;                       // [KTOT][3 gates][32 tiles][4]: {w0,w0,w1,w1}
    float* bi = Wp + KTOT * WKS;          // [RPAD] b_ih (zero-padded)
    float* bh = bi + RPAD;                // [RPAD] b_hh
    float* hx = bh + RPAD;                // [2][KTOT][NB]

    const int tid  = threadIdx.x;
    const int lane = tid & 31;
    const int wid  = tid >> 5;
    const int b0   = blockIdx.x * NB;
    const int tile = wid * 4 + (lane >> 3);   // 0..31 (25 live)
    const int c    = tile * 2;
    const int tb4  = (lane & 7) * 4;          // batch group of 4
    const bool live = (c < HID);

    // ---- one-time: pack weights gate-blocked, scalar-duplicated ----
    for (int i = tid; i < KTOT * WKS; i += NT) {
        int k  = i / WKS;
        int r  = i - k * WKS;
        int g  = r >> 7;            // 0=r,1=z,2=n
        int tl = (r >> 2) & 31;
        int u  = (r >> 1) & 1;
        int cu = tl * 2 + u;
        float v = 0.0f;
        if (cu < HID) {
            int j = g * HID + cu;
            v = (k < HID) ? W_hh[j * HID + k] : W_ih[j * IN_DIM + (k - HID)];
        }
        Wp[i] = v;
    }
    for (int j = tid; j < RPAD; j += NT) {
        bi[j] = (j < ROWS) ? b_ih[j] : 0.0f;
        bh[j] = (j < ROWS) ? b_hh[j] : 0.0f;
    }
    for (int i = tid; i < HID * NB; i += NT) hx[i] = 0.0f;   // zero h rows, buffer 0

    // ---- x duty on warp 7 (all-pad warp): b = lane ----
    float4 xa, xb;
    const float* xrow = nullptr;
    if (wid == 7) {
        xrow = x + (size_t)(b0 + lane) * TLEN * IN_DIM;
        float4 a0 = *(const float4*)&xrow[0];
        float4 a1 = *(const float4*)&xrow[4];
        hx[(HID + 0) * NB + lane] = a0.x; hx[(HID + 1) * NB + lane] = a0.y;
        hx[(HID + 2) * NB + lane] = a0.z; hx[(HID + 3) * NB + lane] = a0.w;
        hx[(HID + 4) * NB + lane] = a1.x; hx[(HID + 5) * NB + lane] = a1.y;
        hx[(HID + 6) * NB + lane] = a1.z; hx[(HID + 7) * NB + lane] = a1.w;
        xa = *(const float4*)&xrow[IN_DIM];
        xb = *(const float4*)&xrow[IN_DIM + 4];
    }
    __syncthreads();

    // bias pairs (duplicated), one-time pk2 outside the loop
    ull bsi[3][2], bbh[3][2];
    #pragma unroll
    for (int g = 0; g < 3; g++)
        #pragma unroll
        for (int u = 0; u < 2; u++) {
            bsi[g][u] = pk2(bi[c + u + 50 * g]);
            bbh[g][u] = pk2(bh[c + u + 50 * g]);
        }

    const float* wbase = Wp + tile * 4;   // per-thread weight base

    for (int t = 0; t < TLEN; t++) {
        float* hcur = hx + (t & 1) * HXS;
        float* hnxt = hx + ((t + 1) & 1) * HXS;

        if (wid != 7) {
            // acc[g][u][p]: gate g, row c+u, batch-pair p
            ull acc[3][2][2];
            #pragma unroll
            for (int g = 0; g < 3; g++)
                #pragma unroll
                for (int u = 0; u < 2; u++) {
                    acc[g][u][0] = bsi[g][u];
                    acc[g][u][1] = bsi[g][u];
                }

            // ---- x-part first (k=50..57), acc init = b_ih ----
            #pragma unroll
            for (int k = HID; k < KTOT; k++) {
                const float* wk = wbase + k * WKS;
                ulonglong2 wr = *(const ulonglong2*)(wk);          // gate r block
                ulonglong2 wz = *(const ulonglong2*)(wk + 128);    // gate z block
                ulonglong2 wn = *(const ulonglong2*)(wk + 256);    // gate n block
                ulonglong2 hp = *(const ulonglong2*)&hcur[k * NB + tb4];
                acc[0][0][0] = ff2(hp.x, wr.x, acc[0][0][0]);
                acc[0][0][1] = ff2(hp.y, wr.x, acc[0][0][1]);
                acc[0][1][0] = ff2(hp.x, wr.y, acc[0][1][0]);
                acc[0][1][1] = ff2(hp.y, wr.y, acc[0][1][1]);
                acc[1][0][0] = ff2(hp.x, wz.x, acc[1][0][0]);
                acc[1][0][1] = ff2(hp.y, wz.x, acc[1][0][1]);
                acc[1][1][0] = ff2(hp.x, wz.y, acc[1][1][0]);
                acc[1][1][1] = ff2(hp.y, wz.y, acc[1][1][1]);
                acc[2][0][0] = ff2(hp.x, wn.x, acc[2][0][0]);
                acc[2][0][1] = ff2(hp.y, wn.x, acc[2][0][1]);
                acc[2][1][0] = ff2(hp.x, wn.y, acc[2][1][0]);
                acc[2][1][1] = ff2(hp.y, wn.y, acc[2][1][1]);
            }
            // snapshot gi_n; add b_hh
            ull gis[2][2];
            #pragma unroll
            for (int u = 0; u < 2; u++) {
                gis[u][0] = acc[2][u][0];
                gis[u][1] = acc[2][u][1];
            }
            #pragma unroll
            for (int g = 0; g < 3; g++)
                #pragma unroll
                for (int u = 0; u < 2; u++) {
                    acc[g][u][0] = add2(acc[g][u][0], bbh[g][u]);
                    acc[g][u][1] = add2(acc[g][u][1], bbh[g][u]);
                }

            // ---- h-part (k=0..49) ----
            #pragma unroll
            for (int k = 0; k < HID; k++) {
                const float* wk = wbase + k * WKS;
                ulonglong2 wr = *(const ulonglong2*)(wk);
                ulonglong2 wz = *(const ulonglong2*)(wk + 128);
                ulonglong2 wn = *(const ulonglong2*)(wk + 256);
                ulonglong2 hp = *(const ulonglong2*)&hcur[k * NB + tb4];
                acc[0][0][0] = ff2(hp.x, wr.x, acc[0][0][0]);
                acc[0][0][1] = ff2(hp.y, wr.x, acc[0][0][1]);
                acc[0][1][0] = ff2(hp.x, wr.y, acc[0][1][0]);
                acc[0][1][1] = ff2(hp.y, wr.y, acc[0][1][1]);
                acc[1][0][0] = ff2(hp.x, wz.x, acc[1][0][0]);
                acc[1][0][1] = ff2(hp.y, wz.x, acc[1][0][1]);
                acc[1][1][0] = ff2(hp.x, wz.y, acc[1][1][0]);
                acc[1][1][1] = ff2(hp.y, wz.y, acc[1][1][1]);
                acc[2][0][0] = ff2(hp.x, wn.x, acc[2][0][0]);
                acc[2][0][1] = ff2(hp.y, wn.x, acc[2][0][1]);
                acc[2][1][0] = ff2(hp.x, wn.y, acc[2][1][0]);
                acc[2][1][1] = ff2(hp.y, wn.y, acc[2][1][1]);
            }

            // ---- gates in-register; write h(t+1) ----
            if (live) {
                #pragma unroll
                for (int u = 0; u < 2; u++) {
                    float4 ho = *(const float4*)&hcur[(c + u) * NB + tb4];
                    const float* o = (const float*)&ho;
                    float hn[4];
                    #pragma unroll
                    for (int p = 0; p < 2; p++) {
                        float2 sr = up2(acc[0][u][p]);
                        float2 sz = up2(acc[1][u][p]);
                        float2 sn = up2(acc[2][u][p]);
                        float2 gi = up2(gis[u][p]);
                        float r0 = fsig(sr.x), z0 = fsig(sz.x);
                        float n0 = tanhapx(sn.x + (r0 - 1.0f) * (sn.x - gi.x));
                        hn[2 * p]     = n0 + z0 * (o[2 * p] - n0);
                        float r1 = fsig(sr.y), z1 = fsig(sz.y);
                        float n1 = tanhapx(sn.y + (r1 - 1.0f) * (sn.y - gi.y));
                        hn[2 * p + 1] = n1 + z1 * (o[2 * p + 1] - n1);
                    }
                    *(float4*)&hnxt[(c + u) * NB + tb4] =
                        make_float4(hn[0], hn[1], hn[2], hn[3]);
                }
            }
        } else {
            // ---- warp 7: publish x_{t+1}; prefetch x_{t+2} ----
            if (t + 1 < TLEN) {
                hnxt[(HID + 0) * NB + lane] = xa.x; hnxt[(HID + 1) * NB + lane] = xa.y;
                hnxt[(HID + 2) * NB + lane] = xa.z; hnxt[(HID + 3) * NB + lane] = xa.w;
                hnxt[(HID + 4) * NB + lane] = xb.x; hnxt[(HID + 5) * NB + lane] = xb.y;
                hnxt[(HID + 6) * NB + lane] = xb.z; hnxt[(HID + 7) * NB + lane] = xb.w;
                if (t + 2 < TLEN) {
                    xa = *(const float4*)&xrow[(size_t)(t + 2) * IN_DIM];
                    xb = *(const float4*)&xrow[(size_t)(t + 2) * IN_DIM + 4];
                }
            }
        }

        __syncthreads();   // the ONLY barrier per step
    }

    // final h lives in buffer 0
    if (tid < NB) {
        float acc = b_out[0];
        #pragma unroll
        for (int cc = 0; cc < HID; cc++) acc += hx[cc * NB + tid] * W_out[cc];
        out[b0 + tid] = acc;
    }
}

extern "C" void kernel_launch(void* const* d_in, const int* in_sizes, int n_in,
                              void* d_out, int out_size) {
    const float* x     = (const float*)d_in[0];
    const float* W_ih  = (const float*)d_in[1];
    const float* W_hh  = (const float*)d_in[2];
    const float* b_ih  = (const float*)d_in[3];
    const float* b_hh  = (const float*)d_in[4];
    const float* W_out = (const float*)d_in[5];
    const float* b_out = (const float*)d_in[6];
    float* out = (float*)d_out;

    size_t smem = (size_t)(KTOT * WKS + 2 * RPAD + 2 * HXS) * sizeof(float);
    cudaFuncSetAttribute(gru_kernel,
                         cudaFuncAttributeMaxDynamicSharedMemorySize, (int)smem);
    gru_kernel<<<GRIDN, NT, smem>>>(x, W_ih, W_hh, b_ih, b_hh, W_out, b_out, out);
}

// round 11
// speedup vs baseline: 1.3093x; 1.3074x over previous
#include <cuda_runtime.h>
#include <math.h>

#define IN_DIM 8
#define HID 50
#define KTOT 58            // 50 h-rows + 8 x-rows unified
#define BATCH 4096
#define TLEN 512
#define ROWS 150
#define RPAD 164
#define NB 32
#define NT 256
#define GRIDN (BATCH / NB)
#define HXS (KTOT * NB)
#define WPROW 256          // Wp row stride: 32 tiles * 8 floats
#define KCH 6              // h-part k=0..5 cached in regs (x-part k=50..57 also cached)

typedef unsigned long long ull;

__device__ __forceinline__ ull pk2(float a) {
    ull r; asm("mov.b64 %0, {%1, %1};" : "=l"(r) : "f"(a)); return r;
}
__device__ __forceinline__ ull ff2(ull a, ull b, ull c) {
    ull d; asm("fma.rn.f32x2 %0, %1, %2, %3;" : "=l"(d) : "l"(a), "l"(b), "l"(c));
    return d;
}
__device__ __forceinline__ ull add2(ull a, ull b) {
    ull d; asm("add.rn.f32x2 %0, %1, %2;" : "=l"(d) : "l"(a), "l"(b));
    return d;
}
__device__ __forceinline__ float2 up2(ull v) {
    float2 r; asm("mov.b64 {%0, %1}, %2;" : "=f"(r.x), "=f"(r.y) : "l"(v)); return r;
}
__device__ __forceinline__ float tanhapx(float v) {
    float r; asm("tanh.approx.f32 %0, %1;" : "=f"(r) : "f"(v)); return r;
}
__device__ __forceinline__ float fsig(float v) {
    return fmaf(0.5f, tanhapx(0.5f * v), 0.5f);
}

__global__ __launch_bounds__(NT, 1) void gru_kernel(
    const float* __restrict__ x, const float* __restrict__ W_ih,
    const float* __restrict__ W_hh, const float* __restrict__ b_ih,
    const float* __restrict__ b_hh, const float* __restrict__ W_out,
    const float* __restrict__ b_out, float* __restrict__ out)
{
    extern __shared__ float sm[];
    float* Wp = sm;                    // [KTOT][32 tiles][8]: wr0,wr1,wz0,wz1,wn0,wn1,pad,pad
    float* bi = Wp + KTOT * WPROW;     // [RPAD]  b_ih (zero-padded)
    float* bh = bi + RPAD;             // [RPAD]  b_hh
    float* hx = bh + RPAD;             // [2][KTOT][NB]  rows 0-49: h, 50-57: x_t

    const int tid  = threadIdx.x;
    const int lane = tid & 31;
    const int wid  = tid >> 5;
    const int b0   = blockIdx.x * NB;
    const int tile = wid * 4 + (lane >> 3);   // 0..31 (25 live)
    const int c    = tile * 2;
    const int tb4  = (lane & 7) * 4;          // batch group of 4
    const bool live = (c < HID);

    // ---- one-time: pack weights gate-interleaved per tile (R6 layout) ----
    for (int i = tid; i < KTOT * WPROW; i += NT) {
        int k = i >> 8;
        int r = i & 255;
        int tl = r >> 3;
        int g  = (r & 7) >> 1;          // 0=r,1=z,2=n,3=pad
        int u  = r & 1;
        int cu = tl * 2 + u;
        float v = 0.0f;
        if (g < 3 && cu < HID) {
            int j = g * HID + cu;
            v = (k < HID) ? W_hh[j * HID + k] : W_ih[j * IN_DIM + (k - HID)];
        }
        Wp[i] = v;
    }
    for (int j = tid; j < RPAD; j += NT) {
        bi[j] = (j < ROWS) ? b_ih[j] : 0.0f;
        bh[j] = (j < ROWS) ? b_hh[j] : 0.0f;
    }
    for (int i = tid; i < HID * NB; i += NT) hx[i] = 0.0f;

    // ---- x duty on warp 7 (all-pad warp): b = lane ----
    float4 xa, xb;
    const float* xrow = nullptr;
    if (wid == 7) {
        xrow = x + (size_t)(b0 + lane) * TLEN * IN_DIM;
        float4 a0 = *(const float4*)&xrow[0];
        float4 a1 = *(const float4*)&xrow[4];
        hx[(HID + 0) * NB + lane] = a0.x; hx[(HID + 1) * NB + lane] = a0.y;
        hx[(HID + 2) * NB + lane] = a0.z; hx[(HID + 3) * NB + lane] = a0.w;
        hx[(HID + 4) * NB + lane] = a1.x; hx[(HID + 5) * NB + lane] = a1.y;
        hx[(HID + 6) * NB + lane] = a1.z; hx[(HID + 7) * NB + lane] = a1.w;
        xa = *(const float4*)&xrow[IN_DIM];
        xb = *(const float4*)&xrow[IN_DIM + 4];
    }
    __syncthreads();

    // bias ulls
    ull bsi[3], bbh[3];
    #pragma unroll
    for (int g = 0; g < 3; g++) {
        bsi[g] = *(const ull*)&bi[c + 50 * g];
        bbh[g] = *(const ull*)&bh[c + 50 * g];
    }

    // ---- loop-invariant W register cache ----
    // cwx[j]: x-part k = 50+j (j=0..7); cwh[j]: h-part k = j (j=0..KCH-1)
    ulonglong2 cwx_rz[8]; ull cwx_n[8];
    ulonglong2 cwh_rz[KCH]; ull cwh_n[KCH];
    #pragma unroll
    for (int j = 0; j < 8; j++) {
        const float* wrow = &Wp[((HID + j) * 32 + tile) * 8];
        cwx_rz[j] = *(const ulonglong2*)wrow;
        cwx_n[j]  = *(const ull*)(wrow + 4);
    }
    #pragma unroll
    for (int j = 0; j < KCH; j++) {
        const float* wrow = &Wp[(j * 32 + tile) * 8];
        cwh_rz[j] = *(const ulonglong2*)wrow;
        cwh_n[j]  = *(const ull*)(wrow + 4);
    }

    for (int t = 0; t < TLEN; t++) {
        float* hcur = hx + (t & 1) * HXS;
        float* hnxt = hx + ((t + 1) & 1) * HXS;

        if (wid != 7) {
            // ---- x-part (k=50..57), acc init = b_ih; W from registers ----
            ull acc[3][4];
            #pragma unroll
            for (int g = 0; g < 3; g++)
                #pragma unroll
                for (int v = 0; v < 4; v++) acc[g][v] = bsi[g];

            #pragma unroll
            for (int j = 0; j < 8; j++) {
                float4 hq = *(const float4*)&hcur[(HID + j) * NB + tb4];
                ull hp[4] = {pk2(hq.x), pk2(hq.y), pk2(hq.z), pk2(hq.w)};
                #pragma unroll
                for (int v = 0; v < 4; v++) {
                    acc[0][v] = ff2(hp[v], cwx_rz[j].x, acc[0][v]);
                    acc[1][v] = ff2(hp[v], cwx_rz[j].y, acc[1][v]);
                    acc[2][v] = ff2(hp[v], cwx_n[j],    acc[2][v]);
                }
            }
            // snapshot gi_n; add b_hh
            ull gis[4];
            #pragma unroll
            for (int v = 0; v < 4; v++) gis[v] = acc[2][v];
            #pragma unroll
            for (int g = 0; g < 3; g++)
                #pragma unroll
                for (int v = 0; v < 4; v++) acc[g][v] = add2(acc[g][v], bbh[g]);

            // ---- h-part k=0..KCH-1: W from registers ----
            #pragma unroll
            for (int j = 0; j < KCH; j++) {
                float4 hq = *(const float4*)&hcur[j * NB + tb4];
                ull hp[4] = {pk2(hq.x), pk2(hq.y), pk2(hq.z), pk2(hq.w)};
                #pragma unroll
                for (int v = 0; v < 4; v++) {
                    acc[0][v] = ff2(hp[v], cwh_rz[j].x, acc[0][v]);
                    acc[1][v] = ff2(hp[v], cwh_rz[j].y, acc[1][v]);
                    acc[2][v] = ff2(hp[v], cwh_n[j],    acc[2][v]);
                }
            }
            // ---- h-part k=KCH..49: W from smem ----
            #pragma unroll
            for (int k = KCH; k < HID; k++) {
                const float* wrow = &Wp[(k * 32 + tile) * 8];
                ulonglong2 wrz = *(const ulonglong2*)wrow;
                ull wn = *(const ull*)(wrow + 4);
                float4 hq = *(const float4*)&hcur[k * NB + tb4];
                ull hp[4] = {pk2(hq.x), pk2(hq.y), pk2(hq.z), pk2(hq.w)};
                #pragma unroll
                for (int v = 0; v < 4; v++) {
                    acc[0][v] = ff2(hp[v], wrz.x, acc[0][v]);
                    acc[1][v] = ff2(hp[v], wrz.y, acc[1][v]);
                    acc[2][v] = ff2(hp[v], wn,    acc[2][v]);
                }
            }

            // ---- gates in-register; write h(t+1) ----
            if (live) {
                float4 ho0 = *(const float4*)&hcur[c * NB + tb4];
                float4 ho1 = *(const float4*)&hcur[(c + 1) * NB + tb4];
                const float* o0 = (const float*)&ho0;
                const float* o1 = (const float*)&ho1;
                float hn0[4], hn1[4];
                #pragma unroll
                for (int v = 0; v < 4; v++) {
                    float2 sr = up2(acc[0][v]);
                    float2 sz = up2(acc[1][v]);
                    float2 sn = up2(acc[2][v]);
                    float2 gi = up2(gis[v]);
                    float r0 = fsig(sr.x), z0 = fsig(sz.x);
                    float n0 = tanhapx(sn.x + (r0 - 1.0f) * (sn.x - gi.x));
                    hn0[v] = n0 + z0 * (o0[v] - n0);
                    float r1 = fsig(sr.y), z1 = fsig(sz.y);
                    float n1 = tanhapx(sn.y + (r1 - 1.0f) * (sn.y - gi.y));
                    hn1[v] = n1 + z1 * (o1[v] - n1);
                }
                *(float4*)&hnxt[c * NB + tb4]       = make_float4(hn0[0], hn0[1], hn0[2], hn0[3]);
                *(float4*)&hnxt[(c + 1) * NB + tb4] = make_float4(hn1[0], hn1[1], hn1[2], hn1[3]);
            }
        } else {
            // ---- warp 7: publish x_{t+1}; prefetch x_{t+2} ----
            if (t + 1 < TLEN) {
                hnxt[(HID + 0) * NB + lane] = xa.x; hnxt[(HID + 1) * NB + lane] = xa.y;
                hnxt[(HID + 2) * NB + lane] = xa.z; hnxt[(HID + 3) * NB + lane] = xa.w;
                hnxt[(HID + 4) * NB + lane] = xb.x; hnxt[(HID + 5) * NB + lane] = xb.y;
                hnxt[(HID + 6) * NB + lane] = xb.z; hnxt[(HID + 7) * NB + lane] = xb.w;
                if (t + 2 < TLEN) {
                    xa = *(const float4*)&xrow[(size_t)(t + 2) * IN_DIM];
                    xb = *(const float4*)&xrow[(size_t)(t + 2) * IN_DIM + 4];
                }
            }
        }

        __syncthreads();   // the ONLY barrier per step
    }

    // final h lives in buffer 0
    if (tid < NB) {
        float acc = b_out[0];
        #pragma unroll
        for (int cc = 0; cc < HID; cc++) acc += hx[cc * NB + tid] * W_out[cc];
        out[b0 + tid] = acc;
    }
}

extern "C" void kernel_launch(void* const* d_in, const int* in_sizes, int n_in,
                              void* d_out, int out_size) {
    const float* x     = (const float*)d_in[0];
    const float* W_ih  = (const float*)d_in[1];
    const float* W_hh  = (const float*)d_in[2];
    const float* b_ih  = (const float*)d_in[3];
    const float* b_hh  = (const float*)d_in[4];
    const float* W_out = (const float*)d_in[5];
    const float* b_out = (const float*)d_in[6];
    float* out = (float*)d_out;

    size_t smem = (size_t)(KTOT * WPROW + 2 * RPAD + 2 * HXS) * sizeof(float);
    cudaFuncSetAttribute(gru_kernel,
                         cudaFuncAttributeMaxDynamicSharedMemorySize, (int)smem);
    gru_kernel<<<GRIDN, NT, smem>>>(x, W_ih, W_hh, b_ih, b_hh, W_out, b_out, out);
}